// round 9
// baseline (speedup 1.0000x reference)
#include <cuda_runtime.h>

#define ND 128
#define HD 256
#define LVLS 4
#define TPB 256
#define PTPB 512          // prep threads
#define NPB 64            // nodes per block tile (96 KB smem -> 2 CTAs/SM)
#define TOTAL_NODES 52400

typedef unsigned long long ull;

__device__ float g_M[LVLS][ND * ND];    // row-major: M[k][j] = (Wv@Wo)[k][j]
__device__ float g_c[LVLS][ND];         // c = bv@Wo
__device__ unsigned char g_mask[TOTAL_NODES];

__device__ __forceinline__ ull ffma2(ull a, ull b, ull c) {
    ull d;
    asm("fma.rn.f32x2 %0, %1, %2, %3;" : "=l"(d) : "l"(a), "l"(b), "l"(c));
    return d;
}
__device__ __forceinline__ float2 upk(ull v) {
    float2 f;
    asm("mov.b64 {%0,%1}, %2;" : "=f"(f.x), "=f"(f.y) : "l"(v));
    return f;
}
__device__ __forceinline__ ull dup2(float a) {
    ull d;
    asm("mov.b64 %0, {%1,%1};" : "=l"(d) : "f"(a));
    return d;
}
__device__ __forceinline__ int sel4(int4 v, int l) {
    return l == 0 ? v.x : l == 1 ? v.y : l == 2 ? v.z : v.w;
}

// Prep: M = Wv@Wo (row-major), c = bv@Wo, + edge-target mask scatter (hidden
// under the latency-bound Wo stream). Mask pre-zeroed by a graph memset node.
__global__ __launch_bounds__(PTPB)
void prep_all_k(const float* __restrict__ Wv, const float* __restrict__ Wo,
                const float* __restrict__ bv, float* __restrict__ M,
                float* __restrict__ cv,
                const int* __restrict__ t0, const int* __restrict__ t1,
                const int* __restrict__ t2, const int* __restrict__ t3,
                int4 ecum4, int4 noff, unsigned char* __restrict__ mask) {
    __shared__ float wv_s[2 * HD];          // 2 Wv rows
    __shared__ float bv_s[HD];
    __shared__ float part[9 * ND];          // quarters 1..3 x (2 rows + c)

    const int tid = threadIdx.x;
    const int lvl = blockIdx.x >> 6, rg = blockIdx.x & 63;
    const int k0 = rg * 2;
    const float* Wvl = Wv + (size_t)lvl * ND * HD;
    const float* Wol = Wo + (size_t)lvl * HD * ND;
    const int j = tid & 127, th = tid >> 7;  // quarter 0..3

    // --- mark scatter: 1 quarter-edge (int4) per thread, fire-and-forget ---
    {
        int i = blockIdx.x * PTPB + tid;
        if (i < ecum4.w) {
            const int* t; int off, no;
            if (i < ecum4.x)      { t = t0; off = 0;       no = noff.x; }
            else if (i < ecum4.y) { t = t1; off = ecum4.x; no = noff.y; }
            else if (i < ecum4.z) { t = t2; off = ecum4.y; no = noff.z; }
            else                  { t = t3; off = ecum4.z; no = noff.w; }
            int4 v = reinterpret_cast<const int4*>(t)[i - off];
            unsigned char* mb = mask + no;
            mb[v.x] = 1; mb[v.y] = 1; mb[v.z] = 1; mb[v.w] = 1;
        }
    }

    // Stage 2 Wv rows + bv (coalesced)
    if (tid < 2 * HD) wv_s[tid] = Wvl[k0 * HD + tid];
    if (tid < HD) bv_s[tid] = bv[lvl * HD + tid];
    __syncthreads();

    // Stream Wo over my t-quarter in explicit 16-wide batches (branch-free).
    const int tBase = th * (HD / 4);
    float acc0 = 0.f, acc1 = 0.f, accc = 0.f;
    #pragma unroll
    for (int tt = 0; tt < HD / 4; tt += 16) {
        float wo[16];
        #pragma unroll
        for (int u = 0; u < 16; u++)
            wo[u] = Wol[(tBase + tt + u) * ND + j];
        #pragma unroll
        for (int u = 0; u < 16; u++) {
            int t = tBase + tt + u;
            acc0 += wv_s[t] * wo[u];
            acc1 += wv_s[HD + t] * wo[u];
            accc += bv_s[t] * wo[u];
        }
    }

    if (th > 0) {
        float* p = part + (th - 1) * 3 * ND;
        p[0 * ND + j] = acc0;
        p[1 * ND + j] = acc1;
        p[2 * ND + j] = accc;
    }
    __syncthreads();
    if (th == 0) {
        #pragma unroll
        for (int q = 0; q < 3; q++) {
            const float* p = part + q * 3 * ND;
            acc0 += p[0 * ND + j];
            acc1 += p[1 * ND + j];
            accc += p[2 * ND + j];
        }
        float* Ml = M + (size_t)lvl * ND * ND;
        Ml[(k0 + 0) * ND + j] = acc0;
        Ml[(k0 + 1) * ND + j] = acc1;
        if (rg == 0) cv[lvl * ND + j] = accc;
    }
}

// GEMM tile 64x128 (2 CTAs/SM) + exact-mask residual + LN epilogue.
__global__ __launch_bounds__(TPB, 2)
void level_all_k(const float* __restrict__ n0i, const float* __restrict__ n1i,
                 const float* __restrict__ n2i, const float* __restrict__ n3i,
                 const unsigned char* __restrict__ mask,
                 const float* __restrict__ Mb, const float* __restrict__ cvb,
                 const float* __restrict__ bob, const float* __restrict__ gb,
                 const float* __restrict__ bb, float* __restrict__ out,
                 int4 bstart, int4 noff, int4 ncnt) {
    extern __shared__ float sm[];
    float* M_s = sm;                        // ND*ND  (M[k][j])  64 KB
    float* A_s = sm + ND * ND;              // NPB*ND (A[node][k]) 32 KB

    const int tid = threadIdx.x;
    const int b = blockIdx.x;

    int lvl, b0;
    if (b < bstart.x)      { lvl = 0; b0 = 0; }
    else if (b < bstart.y) { lvl = 1; b0 = bstart.x; }
    else if (b < bstart.z) { lvl = 2; b0 = bstart.y; }
    else                   { lvl = 3; b0 = bstart.z; }

    const float* nodes = lvl == 0 ? n0i : lvl == 1 ? n1i : lvl == 2 ? n2i : n3i;
    const int N  = sel4(ncnt, lvl);
    const int nO = sel4(noff, lvl);
    const float* Ml = Mb + (size_t)lvl * ND * ND;
    float* outl = out + (size_t)nO * ND;
    const int nodeBase = (b - b0) * NPB;

    // Stage M with float4 (16 LDG.128+STS.128 per thread)
    {
        float4* M_s4 = reinterpret_cast<float4*>(M_s);
        const float4* Ml4 = reinterpret_cast<const float4*>(Ml);
        #pragma unroll
        for (int r = 0; r < 16; r++)
            M_s4[tid + r * TPB] = Ml4[tid + r * TPB];
    }

    // Stage A rows: 64 nodes x 32 float4 (coalesced; OOB rows zero)
    {
        float4* A_s4 = reinterpret_cast<float4*>(A_s);
        const float4* nodes4 = reinterpret_cast<const float4*>(nodes);
        #pragma unroll
        for (int r = 0; r < 8; r++) {
            int idx = tid + r * TPB;        // 0..2047
            int node = idx >> 5, q = idx & 31;
            int gn = nodeBase + node;
            A_s4[idx] = (gn < N) ? nodes4[gn * 32 + q]
                                 : make_float4(0.f, 0.f, 0.f, 0.f);
        }
    }

    const int tc = tid & 15, tr = tid >> 4;
    const int c0a = tc * 4, c0b = 64 + tc * 4;   // two conflict-free col chunks
    const int nloc = tr * 4;                      // 4 nodes per thread

    // Prefetch my 4 mask bytes (epilogue use; latency hidden by mainloop)
    float mk[4];
    #pragma unroll
    for (int u = 0; u < 4; u++) {
        int gn = nodeBase + nloc + u;
        mk[u] = (gn < N && mask[nO + gn]) ? 1.f : 0.f;
    }
    __syncthreads();

    // Mainloop: C[4 nodes][8 cols] += A[4][k] * M[k][8]
    ull acc[4][4];
    #pragma unroll
    for (int u = 0; u < 4; u++)
        #pragma unroll
        for (int c = 0; c < 4; c++) acc[u][c] = 0ull;

    const float* Ar = A_s + nloc * ND;
    #pragma unroll 4
    for (int kk = 0; kk < ND; kk += 4) {
        float4 a[4];
        #pragma unroll
        for (int u = 0; u < 4; u++)
            a[u] = *reinterpret_cast<const float4*>(Ar + u * ND + kk);
        const float* af = reinterpret_cast<const float*>(a);
        #pragma unroll
        for (int t = 0; t < 4; t++) {
            const float* mrow = M_s + (kk + t) * ND;
            ulonglong2 ma = *reinterpret_cast<const ulonglong2*>(mrow + c0a);
            ulonglong2 mb = *reinterpret_cast<const ulonglong2*>(mrow + c0b);
            #pragma unroll
            for (int u = 0; u < 4; u++) {
                ull av2 = dup2(af[u * 4 + t]);
                acc[u][0] = ffma2(av2, ma.x, acc[u][0]);
                acc[u][1] = ffma2(av2, ma.y, acc[u][1]);
                acc[u][2] = ffma2(av2, mb.x, acc[u][2]);
                acc[u][3] = ffma2(av2, mb.y, acc[u][3]);
            }
        }
    }

    // Per-thread params for my 8 columns
    const float* pb = bob + lvl * ND;
    const float* pc = cvb + lvl * ND;
    const float* pg = gb + lvl * ND;
    const float* pp = bb + lvl * ND;
    float4 boA = *reinterpret_cast<const float4*>(pb + c0a);
    float4 boB = *reinterpret_cast<const float4*>(pb + c0b);
    float4 cvA = *reinterpret_cast<const float4*>(pc + c0a);
    float4 cvB = *reinterpret_cast<const float4*>(pc + c0b);
    float4 gA  = *reinterpret_cast<const float4*>(pg + c0a);
    float4 gB  = *reinterpret_cast<const float4*>(pg + c0b);
    float4 bA  = *reinterpret_cast<const float4*>(pp + c0a);
    float4 bB  = *reinterpret_cast<const float4*>(pp + c0b);

    #pragma unroll
    for (int u = 0; u < 4; u++) {
        int node = nloc + u;
        int gn = nodeBase + node;
        float4 r0 = *reinterpret_cast<const float4*>(A_s + node * ND + c0a);
        float4 r1 = *reinterpret_cast<const float4*>(A_s + node * ND + c0b);
        float m = mk[u];
        float x[8];
        float2 p;
        p = upk(acc[u][0]); x[0] = r0.x + boA.x + m * (p.x + cvA.x);
                            x[1] = r0.y + boA.y + m * (p.y + cvA.y);
        p = upk(acc[u][1]); x[2] = r0.z + boA.z + m * (p.x + cvA.z);
                            x[3] = r0.w + boA.w + m * (p.y + cvA.w);
        p = upk(acc[u][2]); x[4] = r1.x + boB.x + m * (p.x + cvB.x);
                            x[5] = r1.y + boB.y + m * (p.y + cvB.y);
        p = upk(acc[u][3]); x[6] = r1.z + boB.z + m * (p.x + cvB.z);
                            x[7] = r1.w + boB.w + m * (p.y + cvB.w);

        float s = 0.f, s2 = 0.f;
        #pragma unroll
        for (int c = 0; c < 8; c++) { s += x[c]; s2 += x[c] * x[c]; }
        #pragma unroll
        for (int o = 8; o > 0; o >>= 1) {   // reduce over the 16-lane tc group
            s  += __shfl_xor_sync(0xffffffffu, s, o);
            s2 += __shfl_xor_sync(0xffffffffu, s2, o);
        }
        float mu = s * (1.f / 128.f);
        float rs = rsqrtf(s2 * (1.f / 128.f) - mu * mu + 1e-5f);

        if (gn < N) {
            float4 o0, o1;
            o0.x = (x[0] - mu) * rs * gA.x + bA.x;
            o0.y = (x[1] - mu) * rs * gA.y + bA.y;
            o0.z = (x[2] - mu) * rs * gA.z + bA.z;
            o0.w = (x[3] - mu) * rs * gA.w + bA.w;
            o1.x = (x[4] - mu) * rs * gB.x + bB.x;
            o1.y = (x[5] - mu) * rs * gB.y + bB.y;
            o1.z = (x[6] - mu) * rs * gB.z + bB.z;
            o1.w = (x[7] - mu) * rs * gB.w + bB.w;
            float* op = outl + (size_t)gn * ND;
            *reinterpret_cast<float4*>(op + c0a) = o0;
            *reinterpret_cast<float4*>(op + c0b) = o1;
        }
    }
}

static const int SMEM_BYTES = (ND + NPB) * ND * (int)sizeof(float);  // 98304

extern "C" void kernel_launch(void* const* d_in, const int* in_sizes, int n_in,
                              void* d_out, int out_size) {
    (void)n_in; (void)out_size;
    int NN[LVLS], NE[LVLS], noffA[LVLS];
    int cumN = 0;
    for (int i = 0; i < LVLS; i++) {
        NN[i] = in_sizes[i * 3] / ND;
        NE[i] = in_sizes[i * 3 + 2] / 2;
        noffA[i] = cumN;
        cumN += NN[i];
    }
    int ec4[LVLS]; int cumE4 = 0;
    for (int i = 0; i < LVLS; i++) { cumE4 += NE[i] / 4; ec4[i] = cumE4; }

    const float* Wv    = (const float*)d_in[16];
    const float* bv    = (const float*)d_in[17];
    const float* Wo    = (const float*)d_in[20];
    const float* bo    = (const float*)d_in[21];
    const float* gamma = (const float*)d_in[22];
    const float* beta  = (const float*)d_in[23];
    float* out = (float*)d_out;

    unsigned char* maskp = nullptr;
    float* Mp = nullptr;
    float* cp = nullptr;
    cudaGetSymbolAddress((void**)&maskp, g_mask);
    cudaGetSymbolAddress((void**)&Mp, g_M);
    cudaGetSymbolAddress((void**)&cp, g_c);

    cudaFuncSetAttribute(level_all_k, cudaFuncAttributeMaxDynamicSharedMemorySize, SMEM_BYTES);

    // 1) zero mask (graph memset node)
    cudaMemsetAsync(maskp, 0, cumN);

    // 2) prep: M/c for all levels + mask marking (hidden under load latency)
    const int* t0 = (const int*)d_in[2]  + NE[0];
    const int* t1 = (const int*)d_in[5]  + NE[1];
    const int* t2 = (const int*)d_in[8]  + NE[2];
    const int* t3 = (const int*)d_in[11] + NE[3];
    int4 ecum4 = make_int4(ec4[0], ec4[1], ec4[2], ec4[3]);
    int4 noff = make_int4(noffA[0], noffA[1], noffA[2], noffA[3]);
    prep_all_k<<<LVLS * 64, PTPB>>>(Wv, Wo, bv, Mp, cp,
                                    t0, t1, t2, t3, ecum4, noff, maskp);

    // 3) fused level kernel (GEMM + exact mask + LN)
    int bs[LVLS], cumB = 0;
    for (int i = 0; i < LVLS; i++) { cumB += (NN[i] + NPB - 1) / NPB; bs[i] = cumB; }
    int4 bstart = make_int4(bs[0], bs[1], bs[2], bs[3]);
    int4 ncnt = make_int4(NN[0], NN[1], NN[2], NN[3]);
    level_all_k<<<cumB, TPB, SMEM_BYTES>>>(
        (const float*)d_in[0], (const float*)d_in[3],
        (const float*)d_in[6], (const float*)d_in[9],
        maskp, Mp, cp, bo, gamma, beta, out, bstart, noff, ncnt);
}

// round 10
// speedup vs baseline: 1.0382x; 1.0382x over previous
#include <cuda_runtime.h>
#include <cuda_bf16.h>
#include <mma.h>
using namespace nvcuda;

#define ND 128
#define HD 256
#define LVLS 4
#define TPB 256
#define PTPB 512          // prep threads
#define NPB 128           // nodes per block tile
#define AST 136           // bf16 smem row stride (pad: 272B, 16B-multiple)
#define CST 132           // fp32 C smem row stride
#define TOTAL_NODES 52400

__device__ __nv_bfloat16 g_Mh[LVLS][ND * ND];  // hi part of M = Wv@Wo, row-major [k][j]
__device__ __nv_bfloat16 g_Ml[LVLS][ND * ND];  // lo part
__device__ float g_c[LVLS][ND];                // c = bv@Wo (fp32)
__device__ unsigned char g_mask[TOTAL_NODES];

__device__ __forceinline__ int sel4(int4 v, int l) {
    return l == 0 ? v.x : l == 1 ? v.y : l == 2 ? v.z : v.w;
}

// Prep: M = Wv@Wo -> bf16 hi/lo, c = bv@Wo, + edge-target mask scatter
// (hidden under the latency-bound Wo stream). Mask pre-zeroed by memset node.
__global__ __launch_bounds__(PTPB)
void prep_all_k(const float* __restrict__ Wv, const float* __restrict__ Wo,
                const float* __restrict__ bv,
                __nv_bfloat16* __restrict__ Mh, __nv_bfloat16* __restrict__ Mlo,
                float* __restrict__ cv,
                const int* __restrict__ t0, const int* __restrict__ t1,
                const int* __restrict__ t2, const int* __restrict__ t3,
                int4 ecum4, int4 noff, unsigned char* __restrict__ mask) {
    __shared__ float wv_s[2 * HD];
    __shared__ float bv_s[HD];
    __shared__ float part[9 * ND];

    const int tid = threadIdx.x;
    const int lvl = blockIdx.x >> 6, rg = blockIdx.x & 63;
    const int k0 = rg * 2;
    const float* Wvl = Wv + (size_t)lvl * ND * HD;
    const float* Wol = Wo + (size_t)lvl * HD * ND;
    const int j = tid & 127, th = tid >> 7;

    // mark scatter: 1 quarter-edge (int4) per thread, fire-and-forget
    {
        int i = blockIdx.x * PTPB + tid;
        if (i < ecum4.w) {
            const int* t; int off, no;
            if (i < ecum4.x)      { t = t0; off = 0;       no = noff.x; }
            else if (i < ecum4.y) { t = t1; off = ecum4.x; no = noff.y; }
            else if (i < ecum4.z) { t = t2; off = ecum4.y; no = noff.z; }
            else                  { t = t3; off = ecum4.z; no = noff.w; }
            int4 v = reinterpret_cast<const int4*>(t)[i - off];
            unsigned char* mb = mask + no;
            mb[v.x] = 1; mb[v.y] = 1; mb[v.z] = 1; mb[v.w] = 1;
        }
    }

    if (tid < 2 * HD) wv_s[tid] = Wvl[k0 * HD + tid];
    if (tid < HD) bv_s[tid] = bv[lvl * HD + tid];
    __syncthreads();

    const int tBase = th * (HD / 4);
    float acc0 = 0.f, acc1 = 0.f, accc = 0.f;
    #pragma unroll
    for (int tt = 0; tt < HD / 4; tt += 16) {
        float wo[16];
        #pragma unroll
        for (int u = 0; u < 16; u++)
            wo[u] = Wol[(tBase + tt + u) * ND + j];
        #pragma unroll
        for (int u = 0; u < 16; u++) {
            int t = tBase + tt + u;
            acc0 += wv_s[t] * wo[u];
            acc1 += wv_s[HD + t] * wo[u];
            accc += bv_s[t] * wo[u];
        }
    }

    if (th > 0) {
        float* p = part + (th - 1) * 3 * ND;
        p[0 * ND + j] = acc0;
        p[1 * ND + j] = acc1;
        p[2 * ND + j] = accc;
    }
    __syncthreads();
    if (th == 0) {
        #pragma unroll
        for (int q = 0; q < 3; q++) {
            const float* p = part + q * 3 * ND;
            acc0 += p[0 * ND + j];
            acc1 += p[1 * ND + j];
            accc += p[2 * ND + j];
        }
        __nv_bfloat16* Mhl = Mh + (size_t)lvl * ND * ND;
        __nv_bfloat16* Mll = Mlo + (size_t)lvl * ND * ND;
        float v0 = acc0, v1 = acc1;
        __nv_bfloat16 h0 = __float2bfloat16(v0);
        __nv_bfloat16 h1 = __float2bfloat16(v1);
        Mhl[(k0 + 0) * ND + j] = h0;
        Mhl[(k0 + 1) * ND + j] = h1;
        Mll[(k0 + 0) * ND + j] = __float2bfloat16(v0 - __bfloat162float(h0));
        Mll[(k0 + 1) * ND + j] = __float2bfloat16(v1 - __bfloat162float(h1));
        if (rg == 0) cv[lvl * ND + j] = accc;
    }
}

// Tensor-core level kernel: bf16 hi/lo split GEMM (3 passes) + mask/residual/LN.
__global__ __launch_bounds__(TPB)
void level_all_k(const float* __restrict__ n0i, const float* __restrict__ n1i,
                 const float* __restrict__ n2i, const float* __restrict__ n3i,
                 const unsigned char* __restrict__ mask,
                 const __nv_bfloat16* __restrict__ Mhb,
                 const __nv_bfloat16* __restrict__ Mlb,
                 const float* __restrict__ cvb, const float* __restrict__ bob,
                 const float* __restrict__ gb, const float* __restrict__ bb,
                 float* __restrict__ out, int4 bstart, int4 noff, int4 ncnt) {
    extern __shared__ char smraw[];
    __nv_bfloat16* Ah   = reinterpret_cast<__nv_bfloat16*>(smraw);   // NPB*AST
    __nv_bfloat16* Al   = Ah + NPB * AST;
    __nv_bfloat16* Mh_s = Al + NPB * AST;                            // ND*AST
    __nv_bfloat16* Ml_s = Mh_s + ND * AST;
    float* C_s = reinterpret_cast<float*>(Mh_s);   // reused after mainloop (67584B <= 69632B)
    float* bo_s = reinterpret_cast<float*>(Ml_s + ND * AST);
    float* cv_s = bo_s + ND;
    float* g_s  = cv_s + ND;
    float* b_s  = g_s + ND;
    float* mk_s = b_s + ND;       // NPB
    float* mu_s = mk_s + NPB;     // NPB
    float* rs_s = mu_s + NPB;     // NPB

    const int tid = threadIdx.x;
    const int b = blockIdx.x;

    int lvl, b0;
    if (b < bstart.x)      { lvl = 0; b0 = 0; }
    else if (b < bstart.y) { lvl = 1; b0 = bstart.x; }
    else if (b < bstart.z) { lvl = 2; b0 = bstart.y; }
    else                   { lvl = 3; b0 = bstart.z; }

    const float* nodes = lvl == 0 ? n0i : lvl == 1 ? n1i : lvl == 2 ? n2i : n3i;
    const int N  = sel4(ncnt, lvl);
    const int nO = sel4(noff, lvl);
    float* outl = out + (size_t)nO * ND;
    const int nodeBase = (b - b0) * NPB;

    // Stage params + mask
    if (tid < ND) {
        bo_s[tid] = bob[lvl * ND + tid];
        cv_s[tid] = cvb[lvl * ND + tid];
        g_s[tid]  = gb[lvl * ND + tid];
        b_s[tid]  = bb[lvl * ND + tid];
    }
    {
        int gn = nodeBase + tid;
        if (tid < NPB) mk_s[tid] = (gn < N && mask[nO + gn]) ? 1.f : 0.f;
    }

    // Stage M bf16 hi/lo into padded smem (uint4 = 8 bf16 per copy)
    {
        const uint4* mh4 = reinterpret_cast<const uint4*>(Mhb + (size_t)lvl * ND * ND);
        const uint4* ml4 = reinterpret_cast<const uint4*>(Mlb + (size_t)lvl * ND * ND);
        #pragma unroll
        for (int r = 0; r < 8; r++) {
            int idx = tid + r * TPB;          // 0..2047 (128 rows x 16 chunks)
            int row = idx >> 4, c8 = idx & 15;
            *reinterpret_cast<uint4*>(Mh_s + row * AST + c8 * 8) = mh4[idx];
            *reinterpret_cast<uint4*>(Ml_s + row * AST + c8 * 8) = ml4[idx];
        }
    }

    // Stage A: fp32 coalesced load -> bf16 hi/lo split
    {
        const float4* nodes4 = reinterpret_cast<const float4*>(nodes);
        #pragma unroll
        for (int r = 0; r < 16; r++) {
            int idx = tid + r * TPB;          // 0..4095 (128 rows x 32 float4)
            int node = idx >> 5, q = idx & 31;
            int gn = nodeBase + node;
            float4 v = (gn < N) ? nodes4[gn * 32 + q]
                                : make_float4(0.f, 0.f, 0.f, 0.f);
            __nv_bfloat16 hx = __float2bfloat16(v.x);
            __nv_bfloat16 hy = __float2bfloat16(v.y);
            __nv_bfloat16 hz = __float2bfloat16(v.z);
            __nv_bfloat16 hw = __float2bfloat16(v.w);
            __nv_bfloat162 hA; hA.x = hx; hA.y = hy;
            __nv_bfloat162 hB; hB.x = hz; hB.y = hw;
            __nv_bfloat162 lA = __floats2bfloat162_rn(v.x - __bfloat162float(hx),
                                                      v.y - __bfloat162float(hy));
            __nv_bfloat162 lB = __floats2bfloat162_rn(v.z - __bfloat162float(hz),
                                                      v.w - __bfloat162float(hw));
            int off = node * AST + q * 4;
            *reinterpret_cast<__nv_bfloat162*>(Ah + off)     = hA;
            *reinterpret_cast<__nv_bfloat162*>(Ah + off + 2) = hB;
            *reinterpret_cast<__nv_bfloat162*>(Al + off)     = lA;
            *reinterpret_cast<__nv_bfloat162*>(Al + off + 2) = lB;
        }
    }
    __syncthreads();

    // Mainloop: 8 warps, warp tile 32 nodes x 64 cols, 3 split-precision passes.
    const int wid = tid >> 5;
    const int wr = wid >> 1, wc = wid & 1;
    wmma::fragment<wmma::accumulator, 16, 16, 16, float> acc[2][4];
    #pragma unroll
    for (int i = 0; i < 2; i++)
        #pragma unroll
        for (int j = 0; j < 4; j++) wmma::fill_fragment(acc[i][j], 0.f);

    #pragma unroll
    for (int p = 0; p < 3; p++) {
        const __nv_bfloat16* Ap = (p == 1) ? Al : Ah;
        const __nv_bfloat16* Mp = (p == 2) ? Ml_s : Mh_s;
        #pragma unroll
        for (int k = 0; k < ND; k += 16) {
            wmma::fragment<wmma::matrix_a, 16, 16, 16, __nv_bfloat16, wmma::row_major> af[2];
            wmma::load_matrix_sync(af[0], Ap + (wr * 32) * AST + k, AST);
            wmma::load_matrix_sync(af[1], Ap + (wr * 32 + 16) * AST + k, AST);
            #pragma unroll
            for (int j = 0; j < 4; j++) {
                wmma::fragment<wmma::matrix_b, 16, 16, 16, __nv_bfloat16, wmma::row_major> bf;
                wmma::load_matrix_sync(bf, Mp + k * AST + wc * 64 + j * 16, AST);
                wmma::mma_sync(acc[0][j], af[0], bf, acc[0][j]);
                wmma::mma_sync(acc[1][j], af[1], bf, acc[1][j]);
            }
        }
    }
    __syncthreads();   // all M reads complete before overwriting region as C_s

    #pragma unroll
    for (int i = 0; i < 2; i++)
        #pragma unroll
        for (int j = 0; j < 4; j++)
            wmma::store_matrix_sync(C_s + (wr * 32 + i * 16) * CST + wc * 64 + j * 16,
                                    acc[i][j], CST, wmma::mem_row_major);
    __syncthreads();

    // LN stats: 2 threads per row (64 cols each), shfl-xor-1 combine
    {
        int row = tid >> 1, half = tid & 1;
        float mk = mk_s[row];
        float s = 0.f, s2 = 0.f;
        int cb = half * 64;
        #pragma unroll 8
        for (int c = 0; c < 64; c++) {
            int col = cb + c;
            float xr = __bfloat162float(Ah[row * AST + col]) +
                       __bfloat162float(Al[row * AST + col]);
            float x = xr + bo_s[col] + mk * (C_s[row * CST + col] + cv_s[col]);
            s += x; s2 += x * x;
        }
        s  += __shfl_xor_sync(0xffffffffu, s, 1);
        s2 += __shfl_xor_sync(0xffffffffu, s2, 1);
        if (half == 0) {
            float mu = s * (1.f / 128.f);
            mu_s[row] = mu;
            rs_s[row] = rsqrtf(s2 * (1.f / 128.f) - mu * mu + 1e-5f);
        }
    }
    __syncthreads();

    // Normalize + affine, coalesced float4 stores
    #pragma unroll
    for (int r = 0; r < 16; r++) {
        int idx = tid + r * TPB;              // 0..4095 float4s
        int row = idx >> 5, q = idx & 31;
        int gn = nodeBase + row;
        if (gn < N) {
            float mk = mk_s[row], mu = mu_s[row], rs = rs_s[row];
            float4 o;
            float* op = &o.x;
            #pragma unroll
            for (int e = 0; e < 4; e++) {
                int col = q * 4 + e;
                float xr = __bfloat162float(Ah[row * AST + col]) +
                           __bfloat162float(Al[row * AST + col]);
                float x = xr + bo_s[col] + mk * (C_s[row * CST + col] + cv_s[col]);
                op[e] = (x - mu) * rs * g_s[col] + b_s[col];
            }
            *reinterpret_cast<float4*>(outl + (size_t)gn * ND + q * 4) = o;
        }
    }
}

static const int SMEM_BYTES = (2 * NPB + 2 * ND) * AST * 2      // bf16 tiles
                            + (4 * ND + 3 * NPB) * (int)sizeof(float);  // params

extern "C" void kernel_launch(void* const* d_in, const int* in_sizes, int n_in,
                              void* d_out, int out_size) {
    (void)n_in; (void)out_size;
    int NN[LVLS], NE[LVLS], noffA[LVLS];
    int cumN = 0;
    for (int i = 0; i < LVLS; i++) {
        NN[i] = in_sizes[i * 3] / ND;
        NE[i] = in_sizes[i * 3 + 2] / 2;
        noffA[i] = cumN;
        cumN += NN[i];
    }
    int ec4[LVLS]; int cumE4 = 0;
    for (int i = 0; i < LVLS; i++) { cumE4 += NE[i] / 4; ec4[i] = cumE4; }

    const float* Wv    = (const float*)d_in[16];
    const float* bv    = (const float*)d_in[17];
    const float* Wo    = (const float*)d_in[20];
    const float* bo    = (const float*)d_in[21];
    const float* gamma = (const float*)d_in[22];
    const float* beta  = (const float*)d_in[23];
    float* out = (float*)d_out;

    unsigned char* maskp = nullptr;
    __nv_bfloat16* Mhp = nullptr;
    __nv_bfloat16* Mlp = nullptr;
    float* cp = nullptr;
    cudaGetSymbolAddress((void**)&maskp, g_mask);
    cudaGetSymbolAddress((void**)&Mhp, g_Mh);
    cudaGetSymbolAddress((void**)&Mlp, g_Ml);
    cudaGetSymbolAddress((void**)&cp, g_c);

    cudaFuncSetAttribute(level_all_k, cudaFuncAttributeMaxDynamicSharedMemorySize, SMEM_BYTES);

    // 1) zero mask
    cudaMemsetAsync(maskp, 0, cumN);

    // 2) prep: M hi/lo bf16 + c + mask marking
    const int* t0 = (const int*)d_in[2]  + NE[0];
    const int* t1 = (const int*)d_in[5]  + NE[1];
    const int* t2 = (const int*)d_in[8]  + NE[2];
    const int* t3 = (const int*)d_in[11] + NE[3];
    int4 ecum4 = make_int4(ec4[0], ec4[1], ec4[2], ec4[3]);
    int4 noff = make_int4(noffA[0], noffA[1], noffA[2], noffA[3]);
    prep_all_k<<<LVLS * 64, PTPB>>>(Wv, Wo, bv, Mhp, Mlp, cp,
                                    t0, t1, t2, t3, ecum4, noff, maskp);

    // 3) tensor-core level kernel
    int bs[LVLS], cumB = 0;
    for (int i = 0; i < LVLS; i++) { cumB += (NN[i] + NPB - 1) / NPB; bs[i] = cumB; }
    int4 bstart = make_int4(bs[0], bs[1], bs[2], bs[3]);
    int4 ncnt = make_int4(NN[0], NN[1], NN[2], NN[3]);
    level_all_k<<<cumB, TPB, SMEM_BYTES>>>(
        (const float*)d_in[0], (const float*)d_in[3],
        (const float*)d_in[6], (const float*)d_in[9],
        maskp, Mhp, Mlp, cp, bo, gamma, beta, out, bstart, noff, ncnt);
}